// round 3
// baseline (speedup 1.0000x reference)
#include <cuda_runtime.h>
#include <cstdint>
#include <cstddef>

// ===================== problem constants =====================
static constexpr int NP      = 50000;     // particles
static constexpr int NPAD    = 50048;     // padded to 391*128
static constexpr int EDG     = 800000;
static constexpr int CAP     = 64;        // slots per receiver (Poisson(16) tail-safe)
static constexpr int KDIM    = 512;       // folded contraction dim: 8 taps * 64 ch
static constexpr int OUTC    = 64;

// ===================== device scratch (no allocs allowed) =====================
__device__ int    g_deg[NPAD];
__device__ int    g_slotS[(size_t)NPAD * CAP];    // sender per slot
__device__ float4 g_w0[(size_t)NPAD * CAP];       // folded weights 0..3 (window applied)
__device__ float4 g_w1[(size_t)NPAD * CAP];       // folded weights 4..7
__device__ float  g_A[(size_t)NPAD * KDIM];       // folded aggregate [NPAD, 512]
__device__ float  g_Bhi[KDIM * OUTC];             // tf32-hi of folded kernel, [k][n]
__device__ float  g_Blo[KDIM * OUTC];             // tf32-lo residual, [k][n]

// ===================== helpers =====================
__device__ __forceinline__ uint32_t f2tf32(float x) {
    uint32_t r;
    asm("cvt.rna.tf32.f32 %0, %1;" : "=r"(r) : "f"(x));
    return r;
}

__device__ __forceinline__ void mma8(float* c, const uint32_t* a, const uint32_t* b) {
    asm volatile(
        "mma.sync.aligned.m16n8k8.row.col.f32.tf32.tf32.f32 "
        "{%0,%1,%2,%3}, {%4,%5,%6,%7}, {%8,%9}, {%0,%1,%2,%3};"
        : "+f"(c[0]), "+f"(c[1]), "+f"(c[2]), "+f"(c[3])
        : "r"(a[0]), "r"(a[1]), "r"(a[2]), "r"(a[3]), "r"(b[0]), "r"(b[1]));
}

// ===================== kernel 1: zero degree counters =====================
__global__ void k_zero_deg() {
    int i = blockIdx.x * blockDim.x + threadIdx.x;
    if (i < NPAD) g_deg[i] = 0;
}

// ===================== kernel 2: bucket edges + precompute folded weights =====================
__global__ void k_fill(const int* __restrict__ recv, const int* __restrict__ snd,
                       const float* __restrict__ rp, const float* __restrict__ ws_p) {
    int e = blockIdx.x * blockDim.x + threadIdx.x;
    if (e >= EDG) return;
    int r = recv[e];
    int slot = atomicAdd(&g_deg[r], 1);
    if (slot >= CAP) return;

    float inv_ws = 1.0f / (*ws_p);
    float px = rp[2 * e], py = rp[2 * e + 1];
    float ux = fminf(fmaxf(px * inv_ws, -1.f), 1.f);
    float uy = fminf(fmaxf(py * inv_ws, -1.f), 1.f);
    float gx = (ux + 1.f) * 1.5f;
    float gy = (uy + 1.f) * 1.5f;
    float x0 = fminf(fmaxf(floorf(gx), 0.f), 2.f);
    float y0 = fminf(fmaxf(floorf(gy), 0.f), 2.f);
    float fx = gx - x0, fy = gy - y0;
    int x0i = (int)x0, y0i = (int)y0;
    float r2 = ux * ux + uy * uy;
    float win = fmaxf(1.f - r2, 0.f);
    win = win * win * win;

    // per-axis weights on full 4-grid, window folded into wx
    float wx[4], wy[4];
    #pragma unroll
    for (int j = 0; j < 4; j++) {
        wx[j] = (j == x0i) ? (1.f - fx) * win : ((j == x0i + 1) ? fx * win : 0.f);
        wy[j] = (j == y0i) ? (1.f - fy)       : ((j == y0i + 1) ? fy       : 0.f);
    }
    // folded tap f (xf=f>>2 in {0,1}, yf=f&3): + (xf,yf) term, - (3-xf,3-yf) term
    float wf[8];
    #pragma unroll
    for (int f = 0; f < 8; f++) {
        int xf = f >> 2, yf = f & 3;
        wf[f] = wx[xf] * wy[yf] - wx[3 - xf] * wy[3 - yf];
    }
    size_t si = (size_t)r * CAP + slot;
    g_slotS[si] = snd[e];
    g_w0[si] = make_float4(wf[0], wf[1], wf[2], wf[3]);
    g_w1[si] = make_float4(wf[4], wf[5], wf[6], wf[7]);
}

// ===================== kernel 3: build folded B, tf32 hi/lo, [k][n] =====================
__global__ void k_buildB(const float* __restrict__ ker) {
    int idx = blockIdx.x * blockDim.x + threadIdx.x;
    if (idx >= KDIM * OUTC) return;
    int k = idx / OUTC;
    int n = idx % OUTC;
    int t = k / 64, i = k % 64;
    int x = t / 4, y = t % 4;
    float v;
    if (y < 2) v = ker[(((x * 2 + y) * 64 + i) * 64) + n];
    else       v = -ker[((((3 - x) * 2 + (3 - y)) * 64 + i) * 64) + n];
    uint32_t hb = f2tf32(v);
    float hi = __uint_as_float(hb);
    uint32_t lb = f2tf32(v - hi);
    g_Bhi[k * OUTC + n] = hi;
    g_Blo[k * OUTC + n] = __uint_as_float(lb);
}

// ===================== kernel 4: per-receiver aggregation, register accumulators =====================
// warp per receiver; lane owns channels (2l, 2l+1); acc[t*2+{0,1}] for 8 folded taps
__global__ void __launch_bounds__(256) k_phase1(const float* __restrict__ feat) {
    int warp = threadIdx.x >> 5, lane = threadIdx.x & 31;
    int r = blockIdx.x * 8 + warp;
    if (r >= NPAD) return;

    int nd = min(g_deg[r], CAP);          // broadcast load
    size_t base = (size_t)r * CAP;

    // cooperative sender prefetch: lane l holds senders for edges l and 32+l
    int sl = (lane < nd)      ? g_slotS[base + lane]      : 0;
    int sh = (32 + lane < nd) ? g_slotS[base + 32 + lane] : 0;

    float acc[16];
    #pragma unroll
    for (int j = 0; j < 16; j++) acc[j] = 0.f;

    if (nd > 0) {
        // software pipeline depth 1
        int    s0 = __shfl_sync(0xFFFFFFFFu, sl, 0);
        float2 f_nx = *(const float2*)(feat + (size_t)s0 * 64 + lane * 2);
        float4 w0_nx = g_w0[base];
        float4 w1_nx = g_w1[base];

        for (int e = 0; e < nd; e++) {
            float2 f = f_nx;
            float4 w0 = w0_nx, w1 = w1_nx;
            int en = e + 1;
            if (en < nd) {
                int sn = (en < 32) ? __shfl_sync(0xFFFFFFFFu, sl, en)
                                   : __shfl_sync(0xFFFFFFFFu, sh, en - 32);
                f_nx = *(const float2*)(feat + (size_t)sn * 64 + lane * 2);
                w0_nx = g_w0[base + en];
                w1_nx = g_w1[base + en];
            }
            acc[0]  += w0.x * f.x;  acc[1]  += w0.x * f.y;
            acc[2]  += w0.y * f.x;  acc[3]  += w0.y * f.y;
            acc[4]  += w0.z * f.x;  acc[5]  += w0.z * f.y;
            acc[6]  += w0.w * f.x;  acc[7]  += w0.w * f.y;
            acc[8]  += w1.x * f.x;  acc[9]  += w1.x * f.y;
            acc[10] += w1.y * f.x;  acc[11] += w1.y * f.y;
            acc[12] += w1.z * f.x;  acc[13] += w1.z * f.y;
            acc[14] += w1.w * f.x;  acc[15] += w1.w * f.y;
        }
    }

    float* dst = g_A + (size_t)r * KDIM + 2 * lane;
    #pragma unroll
    for (int t = 0; t < 8; t++) {
        *(float2*)(dst + t * 64) = make_float2(acc[2 * t], acc[2 * t + 1]);
    }
}

// ===================== kernel 5: tf32 mma.sync GEMM with hi/lo split =====================
// out[NPAD(128/CTA), 64] = A[., 512] @ B[512, 64] + bias
// CTA: 256 thr = 8 warps as 4(M) x 2(N); warp: 32 rows x 32 cols = 2 mtiles x 4 ntiles
static constexpr int KC = 64;                 // K chunk
static constexpr int AST = 68;                // A smem row stride (floats) - conflict-free
static constexpr int BST = 72;                // B smem row stride (floats) - conflict-free
static constexpr int SM_AHI = 0;              // 128*68 = 8704 floats
static constexpr int SM_ALO = 8704;
static constexpr int SM_BHI = 17408;          // 64*72 = 4608 floats
static constexpr int SM_BLO = 22016;
static constexpr int GEMM_SMEM = 26624 * 4;   // 106496 bytes

__global__ void __launch_bounds__(256) k_gemm(const float* __restrict__ bias,
                                              float* __restrict__ out) {
    extern __shared__ float sm[];
    float* sAhi = sm + SM_AHI;
    float* sAlo = sm + SM_ALO;
    float* sBhi = sm + SM_BHI;
    float* sBlo = sm + SM_BLO;

    int tid = threadIdx.x;
    int warp = tid >> 5, lane = tid & 31;
    int gid = lane >> 2, tig = lane & 3;
    int warpM = warp >> 1, warpN = warp & 1;
    int m_base = warpM * 32;
    int n_base = warpN * 32;
    int m0 = blockIdx.x * 128;

    float acc[2][4][4];
    #pragma unroll
    for (int mt = 0; mt < 2; mt++)
        #pragma unroll
        for (int nt = 0; nt < 4; nt++)
            #pragma unroll
            for (int j = 0; j < 4; j++) acc[mt][nt][j] = 0.f;

    const float4* Ag  = (const float4*)g_A;
    const float4* Bhg = (const float4*)g_Bhi;
    const float4* Blg = (const float4*)g_Blo;

    for (int kc = 0; kc < KDIM / KC; kc++) {
        // ---- stage A chunk [128 x 64] with hi/lo split ----
        #pragma unroll
        for (int it = 0; it < 8; it++) {
            int idx = tid + it * 256;               // 0..2047 : 128 rows x 16 float4
            int row = idx >> 4, c4 = idx & 15;
            float4 v = Ag[(size_t)(m0 + row) * 128 + kc * 16 + c4];
            float4 hi, lo;
            {
                uint32_t h;
                h = f2tf32(v.x); hi.x = __uint_as_float(h); lo.x = __uint_as_float(f2tf32(v.x - hi.x));
                h = f2tf32(v.y); hi.y = __uint_as_float(h); lo.y = __uint_as_float(f2tf32(v.y - hi.y));
                h = f2tf32(v.z); hi.z = __uint_as_float(h); lo.z = __uint_as_float(f2tf32(v.z - hi.z));
                h = f2tf32(v.w); hi.w = __uint_as_float(h); lo.w = __uint_as_float(f2tf32(v.w - hi.w));
            }
            ((float4*)(sAhi + row * AST))[c4] = hi;
            ((float4*)(sAlo + row * AST))[c4] = lo;
        }
        // ---- stage B chunk [64 x 64] (pre-split in gmem) ----
        #pragma unroll
        for (int it = 0; it < 4; it++) {
            int idx = tid + it * 256;               // 0..1023 : 64 rows x 16 float4
            int row = idx >> 4, c4 = idx & 15;
            ((float4*)(sBhi + row * BST))[c4] = Bhg[(kc * 64 + row) * 16 + c4];
            ((float4*)(sBlo + row * BST))[c4] = Blg[(kc * 64 + row) * 16 + c4];
        }
        __syncthreads();

        // ---- 8 k-steps of m16n8k8 ----
        #pragma unroll
        for (int ks = 0; ks < 8; ks++) {
            int k0 = ks * 8;
            uint32_t ah[2][4], al[2][4], bh[4][2], bl[4][2];
            #pragma unroll
            for (int mt = 0; mt < 2; mt++) {
                int r0 = m_base + mt * 16 + gid;
                const float* ph = sAhi + r0 * AST + k0 + tig;
                const float* pl = sAlo + r0 * AST + k0 + tig;
                ah[mt][0] = __float_as_uint(ph[0]);
                ah[mt][1] = __float_as_uint(ph[8 * AST]);
                ah[mt][2] = __float_as_uint(ph[4]);
                ah[mt][3] = __float_as_uint(ph[8 * AST + 4]);
                al[mt][0] = __float_as_uint(pl[0]);
                al[mt][1] = __float_as_uint(pl[8 * AST]);
                al[mt][2] = __float_as_uint(pl[4]);
                al[mt][3] = __float_as_uint(pl[8 * AST + 4]);
            }
            #pragma unroll
            for (int nt = 0; nt < 4; nt++) {
                int col = n_base + nt * 8 + gid;
                const float* ph = sBhi + (k0 + tig) * BST + col;
                const float* pl = sBlo + (k0 + tig) * BST + col;
                bh[nt][0] = __float_as_uint(ph[0]);
                bh[nt][1] = __float_as_uint(ph[4 * BST]);
                bl[nt][0] = __float_as_uint(pl[0]);
                bl[nt][1] = __float_as_uint(pl[4 * BST]);
            }
            #pragma unroll
            for (int mt = 0; mt < 2; mt++)
                #pragma unroll
                for (int nt = 0; nt < 4; nt++) {
                    mma8(acc[mt][nt], ah[mt], bh[nt]);
                    mma8(acc[mt][nt], al[mt], bh[nt]);
                    mma8(acc[mt][nt], ah[mt], bl[nt]);
                }
        }
        __syncthreads();
    }

    // ---- epilogue: bias + store ----
    #pragma unroll
    for (int mt = 0; mt < 2; mt++) {
        int r  = m0 + m_base + mt * 16 + gid;
        int r8 = r + 8;
        #pragma unroll
        for (int nt = 0; nt < 4; nt++) {
            int c = n_base + nt * 8 + tig * 2;
            float b0 = __ldg(bias + c), b1 = __ldg(bias + c + 1);
            if (r < NP) {
                float2 v = make_float2(acc[mt][nt][0] + b0, acc[mt][nt][1] + b1);
                *(float2*)(out + (size_t)r * 64 + c) = v;
            }
            if (r8 < NP) {
                float2 v = make_float2(acc[mt][nt][2] + b0, acc[mt][nt][3] + b1);
                *(float2*)(out + (size_t)r8 * 64 + c) = v;
            }
        }
    }
}

// ===================== launch =====================
extern "C" void kernel_launch(void* const* d_in, const int* in_sizes, int n_in,
                              void* d_out, int out_size) {
    const float* feat = (const float*)d_in[0];
    const int*   recv = (const int*)d_in[1];
    const float* rp   = (const float*)d_in[2];
    const float* ws   = (const float*)d_in[3];
    const int*   snd  = (const int*)d_in[4];
    const float* ker  = (const float*)d_in[5];
    const float* bias = (const float*)d_in[6];
    float* out = (float*)d_out;

    cudaFuncSetAttribute(k_gemm, cudaFuncAttributeMaxDynamicSharedMemorySize, GEMM_SMEM);

    k_zero_deg<<<(NPAD + 255) / 256, 256>>>();
    k_fill<<<(EDG + 255) / 256, 256>>>(recv, snd, rp, ws);
    k_buildB<<<(KDIM * OUTC + 255) / 256, 256>>>(ker);
    k_phase1<<<NPAD / 8, 256>>>(feat);
    k_gemm<<<NPAD / 128, 256, GEMM_SMEM>>>(bias, out);
}

// round 4
// speedup vs baseline: 1.1399x; 1.1399x over previous
#include <cuda_runtime.h>
#include <cstdint>
#include <cstddef>

// ===================== problem constants =====================
static constexpr int NP      = 50000;     // particles
static constexpr int NPAD    = 50048;     // padded to 391*128
static constexpr int EDG     = 800000;
static constexpr int CAP     = 64;        // slots per receiver (Poisson(16) tail-safe)
static constexpr int KDIM    = 512;       // folded contraction dim: 8 taps * 64 ch
static constexpr int OUTC    = 64;

// ===================== device scratch (no allocs allowed) =====================
__device__ int    g_deg[NPAD];
__device__ int    g_slotS[(size_t)NPAD * CAP];        // sender per slot
__device__ float4 g_wp[(size_t)NPAD * CAP * 2];       // folded weights, 2 float4 per slot
__device__ float  g_A[(size_t)NPAD * KDIM];           // folded aggregate [NPAD, 512]
__device__ float  g_Bhi[KDIM * OUTC];                 // tf32-hi of folded kernel, [k][n]
__device__ float  g_Blo[KDIM * OUTC];                 // tf32-lo residual, [k][n]

// ===================== helpers =====================
__device__ __forceinline__ uint32_t f2tf32(float x) {
    uint32_t r;
    asm("cvt.rna.tf32.f32 %0, %1;" : "=r"(r) : "f"(x));
    return r;
}

__device__ __forceinline__ void mma8(float* c, const uint32_t* a, const uint32_t* b) {
    asm volatile(
        "mma.sync.aligned.m16n8k8.row.col.f32.tf32.tf32.f32 "
        "{%0,%1,%2,%3}, {%4,%5,%6,%7}, {%8,%9}, {%0,%1,%2,%3};"
        : "+f"(c[0]), "+f"(c[1]), "+f"(c[2]), "+f"(c[3])
        : "r"(a[0]), "r"(a[1]), "r"(a[2]), "r"(a[3]), "r"(b[0]), "r"(b[1]));
}

// ===================== kernel 1: zero degree counters =====================
__global__ void k_zero_deg() {
    int i = blockIdx.x * blockDim.x + threadIdx.x;
    if (i < NPAD) g_deg[i] = 0;
}

// ===================== kernel 2: bucket edges + precompute folded weights =====================
__global__ void k_fill(const int* __restrict__ recv, const int* __restrict__ snd,
                       const float* __restrict__ rp, const float* __restrict__ ws_p) {
    int e = blockIdx.x * blockDim.x + threadIdx.x;
    if (e >= EDG) return;
    int r = recv[e];
    int slot = atomicAdd(&g_deg[r], 1);
    if (slot >= CAP) return;

    float inv_ws = 1.0f / (*ws_p);
    float2 p = ((const float2*)rp)[e];
    float ux = fminf(fmaxf(p.x * inv_ws, -1.f), 1.f);
    float uy = fminf(fmaxf(p.y * inv_ws, -1.f), 1.f);
    float gx = (ux + 1.f) * 1.5f;
    float gy = (uy + 1.f) * 1.5f;
    float x0 = fminf(fmaxf(floorf(gx), 0.f), 2.f);
    float y0 = fminf(fmaxf(floorf(gy), 0.f), 2.f);
    float fx = gx - x0, fy = gy - y0;
    int x0i = (int)x0, y0i = (int)y0;
    float r2 = ux * ux + uy * uy;
    float win = fmaxf(1.f - r2, 0.f);
    win = win * win * win;

    // per-axis weights on full 4-grid, window folded into wx
    float wx[4], wy[4];
    #pragma unroll
    for (int j = 0; j < 4; j++) {
        wx[j] = (j == x0i) ? (1.f - fx) * win : ((j == x0i + 1) ? fx * win : 0.f);
        wy[j] = (j == y0i) ? (1.f - fy)       : ((j == y0i + 1) ? fy       : 0.f);
    }
    // folded tap f (xf=f>>2 in {0,1}, yf=f&3): + (xf,yf) term, - (3-xf,3-yf) term
    float wf[8];
    #pragma unroll
    for (int f = 0; f < 8; f++) {
        int xf = f >> 2, yf = f & 3;
        wf[f] = wx[xf] * wy[yf] - wx[3 - xf] * wy[3 - yf];
    }
    size_t si = (size_t)r * CAP + slot;
    g_slotS[si] = snd[e];
    g_wp[si * 2 + 0] = make_float4(wf[0], wf[1], wf[2], wf[3]);
    g_wp[si * 2 + 1] = make_float4(wf[4], wf[5], wf[6], wf[7]);
}

// ===================== kernel 3: build folded B, tf32 hi/lo, [k][n] =====================
__global__ void k_buildB(const float* __restrict__ ker) {
    int idx = blockIdx.x * blockDim.x + threadIdx.x;
    if (idx >= KDIM * OUTC) return;
    int k = idx / OUTC;
    int n = idx % OUTC;
    int t = k / 64, i = k % 64;
    int x = t / 4, y = t % 4;
    float v;
    if (y < 2) v = ker[(((x * 2 + y) * 64 + i) * 64) + n];
    else       v = -ker[((((3 - x) * 2 + (3 - y)) * 64 + i) * 64) + n];
    uint32_t hb = f2tf32(v);
    float hi = __uint_as_float(hb);
    uint32_t lb = f2tf32(v - hi);
    g_Bhi[k * OUTC + n] = hi;
    g_Blo[k * OUTC + n] = __uint_as_float(lb);
}

// ===================== kernel 4: per-receiver aggregation, unroll-2 / prefetch-2 =====================
// warp per receiver (2 per 64-thr block); lane owns channels (2l, 2l+1)
__global__ void __launch_bounds__(64, 16) k_phase1(const float* __restrict__ feat) {
    int warp = threadIdx.x >> 5, lane = threadIdx.x & 31;
    int r = blockIdx.x * 2 + warp;
    if (r >= NPAD) return;

    int nd = min(g_deg[r], CAP);          // uniform across warp
    size_t base = (size_t)r * CAP;

    float acc[16];
    #pragma unroll
    for (int j = 0; j < 16; j++) acc[j] = 0.f;

    if (nd > 0) {
        // cooperative sender prefetch: lane l holds senders for edges l and 32+l
        int sl = (lane < nd)      ? g_slotS[base + lane]      : 0;
        int sh = (32 + lane < nd) ? g_slotS[base + 32 + lane] : 0;
        int ndm1 = nd - 1;

        float2 fA, fB;
        float4 wA0, wA1, wB0, wB1;

        #define LOAD_E(ei, f, w0, w1) do {                                      \
            int _ec = min((ei), ndm1);                                          \
            int _s = __shfl_sync(0xFFFFFFFFu, (_ec < 32) ? sl : sh, _ec & 31);  \
            (f) = *(const float2*)(feat + (size_t)_s * 64 + lane * 2);          \
            const float4* _wp = &g_wp[(base + _ec) * 2];                        \
            (w0) = _wp[0]; (w1) = _wp[1];                                       \
        } while (0)

        #define FMA_E(f, w0, w1) do {                                           \
            acc[0]  += (w0).x * (f).x;  acc[1]  += (w0).x * (f).y;              \
            acc[2]  += (w0).y * (f).x;  acc[3]  += (w0).y * (f).y;              \
            acc[4]  += (w0).z * (f).x;  acc[5]  += (w0).z * (f).y;              \
            acc[6]  += (w0).w * (f).x;  acc[7]  += (w0).w * (f).y;              \
            acc[8]  += (w1).x * (f).x;  acc[9]  += (w1).x * (f).y;              \
            acc[10] += (w1).y * (f).x;  acc[11] += (w1).y * (f).y;              \
            acc[12] += (w1).z * (f).x;  acc[13] += (w1).z * (f).y;              \
            acc[14] += (w1).w * (f).x;  acc[15] += (w1).w * (f).y;              \
        } while (0)

        LOAD_E(0, fA, wA0, wA1);
        LOAD_E(1, fB, wB0, wB1);

        int e = 0;
        for (; e + 1 < nd; e += 2) {
            float2 f0 = fA, f1 = fB;
            float4 a0 = wA0, a1 = wA1, b0 = wB0, b1 = wB1;
            LOAD_E(e + 2, fA, wA0, wA1);
            LOAD_E(e + 3, fB, wB0, wB1);
            FMA_E(f0, a0, a1);
            FMA_E(f1, b0, b1);
        }
        if (e < nd) {        // odd tail: consume stage A
            FMA_E(fA, wA0, wA1);
        }
        #undef LOAD_E
        #undef FMA_E
    }

    float* dst = g_A + (size_t)r * KDIM + 2 * lane;
    #pragma unroll
    for (int t = 0; t < 8; t++) {
        *(float2*)(dst + t * 64) = make_float2(acc[2 * t], acc[2 * t + 1]);
    }
}

// ===================== kernel 5: tf32 mma.sync GEMM with hi/lo split =====================
// out[NPAD(128/CTA), 64] = A[., 512] @ B[512, 64] + bias
// CTA: 256 thr = 8 warps as 4(M) x 2(N); warp: 32 rows x 32 cols = 2 mtiles x 4 ntiles
static constexpr int KC = 64;                 // K chunk
static constexpr int AST = 68;                // A smem row stride (floats) - conflict-free
static constexpr int BST = 72;                // B smem row stride (floats) - conflict-free
static constexpr int SM_AHI = 0;              // 128*68 = 8704 floats
static constexpr int SM_ALO = 8704;
static constexpr int SM_BHI = 17408;          // 64*72 = 4608 floats
static constexpr int SM_BLO = 22016;
static constexpr int GEMM_SMEM = 26624 * 4;   // 106496 bytes

__global__ void __launch_bounds__(256) k_gemm(const float* __restrict__ bias,
                                              float* __restrict__ out) {
    extern __shared__ float sm[];
    float* sAhi = sm + SM_AHI;
    float* sAlo = sm + SM_ALO;
    float* sBhi = sm + SM_BHI;
    float* sBlo = sm + SM_BLO;

    int tid = threadIdx.x;
    int warp = tid >> 5, lane = tid & 31;
    int gid = lane >> 2, tig = lane & 3;
    int warpM = warp >> 1, warpN = warp & 1;
    int m_base = warpM * 32;
    int n_base = warpN * 32;
    int m0 = blockIdx.x * 128;

    float acc[2][4][4];
    #pragma unroll
    for (int mt = 0; mt < 2; mt++)
        #pragma unroll
        for (int nt = 0; nt < 4; nt++)
            #pragma unroll
            for (int j = 0; j < 4; j++) acc[mt][nt][j] = 0.f;

    const float4* Ag  = (const float4*)g_A;
    const float4* Bhg = (const float4*)g_Bhi;
    const float4* Blg = (const float4*)g_Blo;

    for (int kc = 0; kc < KDIM / KC; kc++) {
        // ---- stage A chunk [128 x 64] with hi/lo split ----
        #pragma unroll
        for (int it = 0; it < 8; it++) {
            int idx = tid + it * 256;               // 0..2047 : 128 rows x 16 float4
            int row = idx >> 4, c4 = idx & 15;
            float4 v = Ag[(size_t)(m0 + row) * 128 + kc * 16 + c4];
            float4 hi, lo;
            {
                uint32_t h;
                h = f2tf32(v.x); hi.x = __uint_as_float(h); lo.x = __uint_as_float(f2tf32(v.x - hi.x));
                h = f2tf32(v.y); hi.y = __uint_as_float(h); lo.y = __uint_as_float(f2tf32(v.y - hi.y));
                h = f2tf32(v.z); hi.z = __uint_as_float(h); lo.z = __uint_as_float(f2tf32(v.z - hi.z));
                h = f2tf32(v.w); hi.w = __uint_as_float(h); lo.w = __uint_as_float(f2tf32(v.w - hi.w));
            }
            ((float4*)(sAhi + row * AST))[c4] = hi;
            ((float4*)(sAlo + row * AST))[c4] = lo;
        }
        // ---- stage B chunk [64 x 64] (pre-split in gmem) ----
        #pragma unroll
        for (int it = 0; it < 4; it++) {
            int idx = tid + it * 256;               // 0..1023 : 64 rows x 16 float4
            int row = idx >> 4, c4 = idx & 15;
            ((float4*)(sBhi + row * BST))[c4] = Bhg[(kc * 64 + row) * 16 + c4];
            ((float4*)(sBlo + row * BST))[c4] = Blg[(kc * 64 + row) * 16 + c4];
        }
        __syncthreads();

        // ---- 8 k-steps of m16n8k8 ----
        #pragma unroll
        for (int ks = 0; ks < 8; ks++) {
            int k0 = ks * 8;
            uint32_t ah[2][4], al[2][4], bh[4][2], bl[4][2];
            #pragma unroll
            for (int mt = 0; mt < 2; mt++) {
                int r0 = m_base + mt * 16 + gid;
                const float* ph = sAhi + r0 * AST + k0 + tig;
                const float* pl = sAlo + r0 * AST + k0 + tig;
                ah[mt][0] = __float_as_uint(ph[0]);
                ah[mt][1] = __float_as_uint(ph[8 * AST]);
                ah[mt][2] = __float_as_uint(ph[4]);
                ah[mt][3] = __float_as_uint(ph[8 * AST + 4]);
                al[mt][0] = __float_as_uint(pl[0]);
                al[mt][1] = __float_as_uint(pl[8 * AST]);
                al[mt][2] = __float_as_uint(pl[4]);
                al[mt][3] = __float_as_uint(pl[8 * AST + 4]);
            }
            #pragma unroll
            for (int nt = 0; nt < 4; nt++) {
                int col = n_base + nt * 8 + gid;
                const float* ph = sBhi + (k0 + tig) * BST + col;
                const float* pl = sBlo + (k0 + tig) * BST + col;
                bh[nt][0] = __float_as_uint(ph[0]);
                bh[nt][1] = __float_as_uint(ph[4 * BST]);
                bl[nt][0] = __float_as_uint(pl[0]);
                bl[nt][1] = __float_as_uint(pl[4 * BST]);
            }
            #pragma unroll
            for (int mt = 0; mt < 2; mt++)
                #pragma unroll
                for (int nt = 0; nt < 4; nt++) {
                    mma8(acc[mt][nt], ah[mt], bh[nt]);
                    mma8(acc[mt][nt], al[mt], bh[nt]);
                    mma8(acc[mt][nt], ah[mt], bl[nt]);
                }
        }
        __syncthreads();
    }

    // ---- epilogue: bias + store ----
    #pragma unroll
    for (int mt = 0; mt < 2; mt++) {
        int r  = m0 + m_base + mt * 16 + gid;
        int r8 = r + 8;
        #pragma unroll
        for (int nt = 0; nt < 4; nt++) {
            int c = n_base + nt * 8 + tig * 2;
            float b0 = __ldg(bias + c), b1 = __ldg(bias + c + 1);
            if (r < NP) {
                float2 v = make_float2(acc[mt][nt][0] + b0, acc[mt][nt][1] + b1);
                *(float2*)(out + (size_t)r * 64 + c) = v;
            }
            if (r8 < NP) {
                float2 v = make_float2(acc[mt][nt][2] + b0, acc[mt][nt][3] + b1);
                *(float2*)(out + (size_t)r8 * 64 + c) = v;
            }
        }
    }
}

// ===================== launch =====================
extern "C" void kernel_launch(void* const* d_in, const int* in_sizes, int n_in,
                              void* d_out, int out_size) {
    const float* feat = (const float*)d_in[0];
    const int*   recv = (const int*)d_in[1];
    const float* rp   = (const float*)d_in[2];
    const float* ws   = (const float*)d_in[3];
    const int*   snd  = (const int*)d_in[4];
    const float* ker  = (const float*)d_in[5];
    const float* bias = (const float*)d_in[6];
    float* out = (float*)d_out;

    cudaFuncSetAttribute(k_gemm, cudaFuncAttributeMaxDynamicSharedMemorySize, GEMM_SMEM);

    k_zero_deg<<<(NPAD + 255) / 256, 256>>>();
    k_fill<<<(EDG + 255) / 256, 256>>>(recv, snd, rp, ws);
    k_buildB<<<(KDIM * OUTC + 255) / 256, 256>>>(ker);
    k_phase1<<<NPAD / 2, 64>>>(feat);
    k_gemm<<<NPAD / 128, 256, GEMM_SMEM>>>(bias, out);
}

// round 5
// speedup vs baseline: 1.2066x; 1.0584x over previous
#include <cuda_runtime.h>
#include <cstdint>
#include <cstddef>

// ===================== problem constants =====================
static constexpr int NP      = 50000;     // particles
static constexpr int NPAD    = 50048;     // padded to 391*128
static constexpr int EDG     = 800000;
static constexpr int CAP     = 64;        // slots per receiver (Poisson(16) tail-safe)
static constexpr int KDIM    = 512;       // folded contraction dim: 8 taps * 64 ch
static constexpr int OUTC    = 64;
static constexpr int PD      = 8;         // phase1 cp.async pipeline depth

// ===================== device scratch (no allocs allowed) =====================
__device__ int    g_deg[NPAD];
__device__ int    g_slotS[(size_t)NPAD * CAP];        // sender per slot
__device__ float4 g_wp[(size_t)NPAD * CAP * 2];       // folded weights, 2 float4 per slot
__device__ float  g_A[(size_t)NPAD * KDIM];           // folded aggregate [NPAD, 512]
__device__ float  g_Bhi[KDIM * OUTC];                 // tf32-hi of folded kernel, [k][n]
__device__ float  g_Blo[KDIM * OUTC];                 // tf32-lo residual, [k][n]

// ===================== helpers =====================
__device__ __forceinline__ uint32_t f2tf32(float x) {
    uint32_t r;
    asm("cvt.rna.tf32.f32 %0, %1;" : "=r"(r) : "f"(x));
    return r;
}

__device__ __forceinline__ uint32_t smem_u32(const void* p) {
    return (uint32_t)__cvta_generic_to_shared(p);
}

__device__ __forceinline__ void mma8(float* c, const uint32_t* a, const uint32_t* b) {
    asm volatile(
        "mma.sync.aligned.m16n8k8.row.col.f32.tf32.tf32.f32 "
        "{%0,%1,%2,%3}, {%4,%5,%6,%7}, {%8,%9}, {%0,%1,%2,%3};"
        : "+f"(c[0]), "+f"(c[1]), "+f"(c[2]), "+f"(c[3])
        : "r"(a[0]), "r"(a[1]), "r"(a[2]), "r"(a[3]), "r"(b[0]), "r"(b[1]));
}

// ===================== kernel 1: zero degree counters =====================
__global__ void k_zero_deg() {
    int i = blockIdx.x * blockDim.x + threadIdx.x;
    if (i < NPAD) g_deg[i] = 0;
}

// ===================== kernel 2: bucket edges + precompute folded weights =====================
__global__ void k_fill(const int* __restrict__ recv, const int* __restrict__ snd,
                       const float* __restrict__ rp, const float* __restrict__ ws_p) {
    int e = blockIdx.x * blockDim.x + threadIdx.x;
    if (e >= EDG) return;
    int r = recv[e];
    int slot = atomicAdd(&g_deg[r], 1);
    if (slot >= CAP) return;

    float inv_ws = 1.0f / (*ws_p);
    float2 p = ((const float2*)rp)[e];
    float ux = fminf(fmaxf(p.x * inv_ws, -1.f), 1.f);
    float uy = fminf(fmaxf(p.y * inv_ws, -1.f), 1.f);
    float gx = (ux + 1.f) * 1.5f;
    float gy = (uy + 1.f) * 1.5f;
    float x0 = fminf(fmaxf(floorf(gx), 0.f), 2.f);
    float y0 = fminf(fmaxf(floorf(gy), 0.f), 2.f);
    float fx = gx - x0, fy = gy - y0;
    int x0i = (int)x0, y0i = (int)y0;
    float r2 = ux * ux + uy * uy;
    float win = fmaxf(1.f - r2, 0.f);
    win = win * win * win;

    // per-axis weights on full 4-grid, window folded into wx
    float wx[4], wy[4];
    #pragma unroll
    for (int j = 0; j < 4; j++) {
        wx[j] = (j == x0i) ? (1.f - fx) * win : ((j == x0i + 1) ? fx * win : 0.f);
        wy[j] = (j == y0i) ? (1.f - fy)       : ((j == y0i + 1) ? fy       : 0.f);
    }
    // folded tap f (xf=f>>2 in {0,1}, yf=f&3): + (xf,yf) term, - (3-xf,3-yf) term
    float wf[8];
    #pragma unroll
    for (int f = 0; f < 8; f++) {
        int xf = f >> 2, yf = f & 3;
        wf[f] = wx[xf] * wy[yf] - wx[3 - xf] * wy[3 - yf];
    }
    size_t si = (size_t)r * CAP + slot;
    g_slotS[si] = snd[e];
    g_wp[si * 2 + 0] = make_float4(wf[0], wf[1], wf[2], wf[3]);
    g_wp[si * 2 + 1] = make_float4(wf[4], wf[5], wf[6], wf[7]);
}

// ===================== kernel 3: build folded B, tf32 hi/lo, [k][n] =====================
__global__ void k_buildB(const float* __restrict__ ker) {
    int idx = blockIdx.x * blockDim.x + threadIdx.x;
    if (idx >= KDIM * OUTC) return;
    int k = idx / OUTC;
    int n = idx % OUTC;
    int t = k / 64, i = k % 64;
    int x = t / 4, y = t % 4;
    float v;
    if (y < 2) v = ker[(((x * 2 + y) * 64 + i) * 64) + n];
    else       v = -ker[((((3 - x) * 2 + (3 - y)) * 64 + i) * 64) + n];
    uint32_t hb = f2tf32(v);
    float hi = __uint_as_float(hb);
    uint32_t lb = f2tf32(v - hi);
    g_Bhi[k * OUTC + n] = hi;
    g_Blo[k * OUTC + n] = __uint_as_float(lb);
}

// ===================== kernel 4: per-receiver aggregation, cp.async smem pipeline =====================
// warp per receiver (2 per 64-thr block); lane owns channels (2l, 2l+1)
// per-warp ring of PD stages: 256B feature row + 32B folded weights, staged by ONE
// cp.async instruction per edge (lanes 0-15: feat, lanes 16-17: weights).
__global__ void __launch_bounds__(64) k_phase1(const float* __restrict__ feat) {
    __shared__ float sFeat[2][PD][64];
    __shared__ float sW[2][PD][8];

    int warp = threadIdx.x >> 5, lane = threadIdx.x & 31;
    int r = blockIdx.x * 2 + warp;          // grid = NPAD/2 exactly
    int nd = min(g_deg[r], CAP);            // uniform across warp
    size_t base = (size_t)r * CAP;

    // cooperative sender preload: lane l holds senders for edges l and 32+l
    int sl = (lane < nd)      ? g_slotS[base + lane]      : 0;
    int sh = (32 + lane < nd) ? g_slotS[base + 32 + lane] : 0;

    float acc[16];
    #pragma unroll
    for (int j = 0; j < 16; j++) acc[j] = 0.f;

    // stage issue: edge e -> ring buffer e & (PD-1); empty commit past nd
    #define ISSUE(e) do {                                                        \
        int _e = (e);                                                            \
        if (_e < nd) {                                                           \
            int _j = _e & (PD - 1);                                              \
            int _s = __shfl_sync(0xFFFFFFFFu, (_e < 32) ? sl : sh, _e & 31);     \
            if (lane < 16) {                                                     \
                const float4* _src = (const float4*)(feat + (size_t)_s * 64) + lane; \
                uint32_t _dst = smem_u32(&sFeat[warp][_j][lane * 4]);            \
                asm volatile("cp.async.ca.shared.global [%0], [%1], 16;"         \
                             :: "r"(_dst), "l"(_src) : "memory");                \
            } else if (lane < 18) {                                              \
                const float4* _src = &g_wp[(base + _e) * 2 + (lane - 16)];       \
                uint32_t _dst = smem_u32(&sW[warp][_j][(lane - 16) * 4]);        \
                asm volatile("cp.async.ca.shared.global [%0], [%1], 16;"         \
                             :: "r"(_dst), "l"(_src) : "memory");                \
            }                                                                    \
        }                                                                        \
        asm volatile("cp.async.commit_group;" ::: "memory");                     \
    } while (0)

    #pragma unroll
    for (int j = 0; j < PD; j++) ISSUE(j);

    for (int e = 0; e < nd; e++) {
        asm volatile("cp.async.wait_group %0;" :: "n"(PD - 1) : "memory");
        __syncwarp();
        int jb = e & (PD - 1);
        float2 f  = *(const float2*)&sFeat[warp][jb][lane * 2];
        float4 w0 = *(const float4*)&sW[warp][jb][0];
        float4 w1 = *(const float4*)&sW[warp][jb][4];
        acc[0]  += w0.x * f.x;  acc[1]  += w0.x * f.y;
        acc[2]  += w0.y * f.x;  acc[3]  += w0.y * f.y;
        acc[4]  += w0.z * f.x;  acc[5]  += w0.z * f.y;
        acc[6]  += w0.w * f.x;  acc[7]  += w0.w * f.y;
        acc[8]  += w1.x * f.x;  acc[9]  += w1.x * f.y;
        acc[10] += w1.y * f.x;  acc[11] += w1.y * f.y;
        acc[12] += w1.z * f.x;  acc[13] += w1.z * f.y;
        acc[14] += w1.w * f.x;  acc[15] += w1.w * f.y;
        __syncwarp();                 // reads done before ring slot reuse
        ISSUE(e + PD);
    }
    #undef ISSUE

    float* dst = g_A + (size_t)r * KDIM + 2 * lane;
    #pragma unroll
    for (int t = 0; t < 8; t++) {
        *(float2*)(dst + t * 64) = make_float2(acc[2 * t], acc[2 * t + 1]);
    }
}

// ===================== kernel 5: tf32 mma.sync GEMM with hi/lo split =====================
// out[NPAD(128/CTA), 64] = A[., 512] @ B[512, 64] + bias
// CTA: 256 thr = 8 warps as 4(M) x 2(N); warp: 32 rows x 32 cols = 2 mtiles x 4 ntiles
static constexpr int KC = 64;                 // K chunk
static constexpr int AST = 68;                // A smem row stride (floats) - conflict-free
static constexpr int BST = 72;                // B smem row stride (floats) - conflict-free
static constexpr int SM_AHI = 0;              // 128*68 = 8704 floats
static constexpr int SM_ALO = 8704;
static constexpr int SM_BHI = 17408;          // 64*72 = 4608 floats
static constexpr int SM_BLO = 22016;
static constexpr int GEMM_SMEM = 26624 * 4;   // 106496 bytes

__global__ void __launch_bounds__(256) k_gemm(const float* __restrict__ bias,
                                              float* __restrict__ out) {
    extern __shared__ float sm[];
    float* sAhi = sm + SM_AHI;
    float* sAlo = sm + SM_ALO;
    float* sBhi = sm + SM_BHI;
    float* sBlo = sm + SM_BLO;

    int tid = threadIdx.x;
    int warp = tid >> 5, lane = tid & 31;
    int gid = lane >> 2, tig = lane & 3;
    int warpM = warp >> 1, warpN = warp & 1;
    int m_base = warpM * 32;
    int n_base = warpN * 32;
    int m0 = blockIdx.x * 128;

    float acc[2][4][4];
    #pragma unroll
    for (int mt = 0; mt < 2; mt++)
        #pragma unroll
        for (int nt = 0; nt < 4; nt++)
            #pragma unroll
            for (int j = 0; j < 4; j++) acc[mt][nt][j] = 0.f;

    const float4* Ag  = (const float4*)g_A;
    const float4* Bhg = (const float4*)g_Bhi;
    const float4* Blg = (const float4*)g_Blo;

    for (int kc = 0; kc < KDIM / KC; kc++) {
        // ---- stage A chunk [128 x 64] with hi/lo split ----
        #pragma unroll
        for (int it = 0; it < 8; it++) {
            int idx = tid + it * 256;               // 0..2047 : 128 rows x 16 float4
            int row = idx >> 4, c4 = idx & 15;
            float4 v = Ag[(size_t)(m0 + row) * 128 + kc * 16 + c4];
            float4 hi, lo;
            {
                uint32_t h;
                h = f2tf32(v.x); hi.x = __uint_as_float(h); lo.x = __uint_as_float(f2tf32(v.x - hi.x));
                h = f2tf32(v.y); hi.y = __uint_as_float(h); lo.y = __uint_as_float(f2tf32(v.y - hi.y));
                h = f2tf32(v.z); hi.z = __uint_as_float(h); lo.z = __uint_as_float(f2tf32(v.z - hi.z));
                h = f2tf32(v.w); hi.w = __uint_as_float(h); lo.w = __uint_as_float(f2tf32(v.w - hi.w));
            }
            ((float4*)(sAhi + row * AST))[c4] = hi;
            ((float4*)(sAlo + row * AST))[c4] = lo;
        }
        // ---- stage B chunk [64 x 64] (pre-split in gmem) ----
        #pragma unroll
        for (int it = 0; it < 4; it++) {
            int idx = tid + it * 256;               // 0..1023 : 64 rows x 16 float4
            int row = idx >> 4, c4 = idx & 15;
            ((float4*)(sBhi + row * BST))[c4] = Bhg[(kc * 64 + row) * 16 + c4];
            ((float4*)(sBlo + row * BST))[c4] = Blg[(kc * 64 + row) * 16 + c4];
        }
        __syncthreads();

        // ---- 8 k-steps of m16n8k8 ----
        #pragma unroll
        for (int ks = 0; ks < 8; ks++) {
            int k0 = ks * 8;
            uint32_t ah[2][4], al[2][4], bh[4][2], bl[4][2];
            #pragma unroll
            for (int mt = 0; mt < 2; mt++) {
                int r0 = m_base + mt * 16 + gid;
                const float* ph = sAhi + r0 * AST + k0 + tig;
                const float* pl = sAlo + r0 * AST + k0 + tig;
                ah[mt][0] = __float_as_uint(ph[0]);
                ah[mt][1] = __float_as_uint(ph[8 * AST]);
                ah[mt][2] = __float_as_uint(ph[4]);
                ah[mt][3] = __float_as_uint(ph[8 * AST + 4]);
                al[mt][0] = __float_as_uint(pl[0]);
                al[mt][1] = __float_as_uint(pl[8 * AST]);
                al[mt][2] = __float_as_uint(pl[4]);
                al[mt][3] = __float_as_uint(pl[8 * AST + 4]);
            }
            #pragma unroll
            for (int nt = 0; nt < 4; nt++) {
                int col = n_base + nt * 8 + gid;
                const float* ph = sBhi + (k0 + tig) * BST + col;
                const float* pl = sBlo + (k0 + tig) * BST + col;
                bh[nt][0] = __float_as_uint(ph[0]);
                bh[nt][1] = __float_as_uint(ph[4 * BST]);
                bl[nt][0] = __float_as_uint(pl[0]);
                bl[nt][1] = __float_as_uint(pl[4 * BST]);
            }
            #pragma unroll
            for (int mt = 0; mt < 2; mt++)
                #pragma unroll
                for (int nt = 0; nt < 4; nt++) {
                    mma8(acc[mt][nt], ah[mt], bh[nt]);
                    mma8(acc[mt][nt], al[mt], bh[nt]);
                    mma8(acc[mt][nt], ah[mt], bl[nt]);
                }
        }
        __syncthreads();
    }

    // ---- epilogue: bias + store ----
    #pragma unroll
    for (int mt = 0; mt < 2; mt++) {
        int r  = m0 + m_base + mt * 16 + gid;
        int r8 = r + 8;
        #pragma unroll
        for (int nt = 0; nt < 4; nt++) {
            int c = n_base + nt * 8 + tig * 2;
            float b0 = __ldg(bias + c), b1 = __ldg(bias + c + 1);
            if (r < NP) {
                float2 v = make_float2(acc[mt][nt][0] + b0, acc[mt][nt][1] + b1);
                *(float2*)(out + (size_t)r * 64 + c) = v;
            }
            if (r8 < NP) {
                float2 v = make_float2(acc[mt][nt][2] + b0, acc[mt][nt][3] + b1);
                *(float2*)(out + (size_t)r8 * 64 + c) = v;
            }
        }
    }
}

// ===================== launch =====================
extern "C" void kernel_launch(void* const* d_in, const int* in_sizes, int n_in,
                              void* d_out, int out_size) {
    const float* feat = (const float*)d_in[0];
    const int*   recv = (const int*)d_in[1];
    const float* rp   = (const float*)d_in[2];
    const float* ws   = (const float*)d_in[3];
    const int*   snd  = (const int*)d_in[4];
    const float* ker  = (const float*)d_in[5];
    const float* bias = (const float*)d_in[6];
    float* out = (float*)d_out;

    cudaFuncSetAttribute(k_gemm, cudaFuncAttributeMaxDynamicSharedMemorySize, GEMM_SMEM);

    k_zero_deg<<<(NPAD + 255) / 256, 256>>>();
    k_fill<<<(EDG + 255) / 256, 256>>>(recv, snd, rp, ws);
    k_buildB<<<(KDIM * OUTC + 255) / 256, 256>>>(ker);
    k_phase1<<<NPAD / 2, 64>>>(feat);
    k_gemm<<<NPAD / 128, 256, GEMM_SMEM>>>(bias, out);
}

// round 7
// speedup vs baseline: 1.2200x; 1.0112x over previous
#include <cuda_runtime.h>
#include <cstdint>
#include <cstddef>

// ===================== problem constants =====================
static constexpr int NP      = 50000;     // particles
static constexpr int NPAD    = 50048;     // padded to 391*128
static constexpr int EDG     = 800000;
static constexpr int CAP     = 64;        // slots per receiver (Poisson(16) tail-safe)
static constexpr int KDIM    = 512;       // folded contraction dim: 8 taps * 64 ch
static constexpr int OUTC    = 64;
static constexpr int PD      = 8;         // phase1 cp.async pipeline depth

// ===================== device scratch (no allocs allowed) =====================
__device__ int    g_deg[NPAD];
__device__ int    g_slotS[(size_t)NPAD * CAP];        // sender per slot
__device__ float4 g_wp[(size_t)NPAD * CAP * 2];       // folded weights, 2 float4 per slot
__device__ float  g_A[(size_t)NPAD * KDIM];           // folded aggregate [NPAD, 512]
__device__ float  g_Bhi[OUTC * KDIM];                 // tf32-hi folded kernel, [n][k]
__device__ float  g_Blo[OUTC * KDIM];                 // tf32-lo residual,      [n][k]

// ===================== helpers =====================
__device__ __forceinline__ uint32_t f2tf32(float x) {
    uint32_t r;
    asm("cvt.rna.tf32.f32 %0, %1;" : "=r"(r) : "f"(x));
    return r;
}

__device__ __forceinline__ uint32_t smem_u32(const void* p) {
    return (uint32_t)__cvta_generic_to_shared(p);
}

__device__ __forceinline__ void mma8(float* c, const uint32_t* a, const uint32_t* b) {
    asm volatile(
        "mma.sync.aligned.m16n8k8.row.col.f32.tf32.tf32.f32 "
        "{%0,%1,%2,%3}, {%4,%5,%6,%7}, {%8,%9}, {%0,%1,%2,%3};"
        : "+f"(c[0]), "+f"(c[1]), "+f"(c[2]), "+f"(c[3])
        : "r"(a[0]), "r"(a[1]), "r"(a[2]), "r"(a[3]), "r"(b[0]), "r"(b[1]));
}

__device__ __forceinline__ void ldsm4(uint32_t* r, uint32_t addr) {
    asm volatile("ldmatrix.sync.aligned.m8n8.x4.shared.b16 {%0,%1,%2,%3}, [%4];"
                 : "=r"(r[0]), "=r"(r[1]), "=r"(r[2]), "=r"(r[3]) : "r"(addr));
}

// ===================== kernel 1: zero degree counters =====================
__global__ void k_zero_deg() {
    int i = blockIdx.x * blockDim.x + threadIdx.x;
    if (i < NPAD) g_deg[i] = 0;
}

// ===================== kernel 2: bucket edges + precompute folded weights =====================
__global__ void k_fill(const int* __restrict__ recv, const int* __restrict__ snd,
                       const float* __restrict__ rp, const float* __restrict__ ws_p) {
    int e = blockIdx.x * blockDim.x + threadIdx.x;
    if (e >= EDG) return;
    int r = recv[e];
    int slot = atomicAdd(&g_deg[r], 1);
    if (slot >= CAP) return;

    float inv_ws = 1.0f / (*ws_p);
    float2 p = ((const float2*)rp)[e];
    float ux = fminf(fmaxf(p.x * inv_ws, -1.f), 1.f);
    float uy = fminf(fmaxf(p.y * inv_ws, -1.f), 1.f);
    float gx = (ux + 1.f) * 1.5f;
    float gy = (uy + 1.f) * 1.5f;
    float x0 = fminf(fmaxf(floorf(gx), 0.f), 2.f);
    float y0 = fminf(fmaxf(floorf(gy), 0.f), 2.f);
    float fx = gx - x0, fy = gy - y0;
    int x0i = (int)x0, y0i = (int)y0;
    float r2 = ux * ux + uy * uy;
    float win = fmaxf(1.f - r2, 0.f);
    win = win * win * win;

    float wx[4], wy[4];
    #pragma unroll
    for (int j = 0; j < 4; j++) {
        wx[j] = (j == x0i) ? (1.f - fx) * win : ((j == x0i + 1) ? fx * win : 0.f);
        wy[j] = (j == y0i) ? (1.f - fy)       : ((j == y0i + 1) ? fy       : 0.f);
    }
    float wf[8];
    #pragma unroll
    for (int f = 0; f < 8; f++) {
        int xf = f >> 2, yf = f & 3;
        wf[f] = wx[xf] * wy[yf] - wx[3 - xf] * wy[3 - yf];
    }
    size_t si = (size_t)r * CAP + slot;
    g_slotS[si] = snd[e];
    g_wp[si * 2 + 0] = make_float4(wf[0], wf[1], wf[2], wf[3]);
    g_wp[si * 2 + 1] = make_float4(wf[4], wf[5], wf[6], wf[7]);
}

// ===================== kernel 3: build folded B, tf32 hi/lo, [n][k] layout =====================
__global__ void k_buildB(const float* __restrict__ ker) {
    int idx = blockIdx.x * blockDim.x + threadIdx.x;
    if (idx >= KDIM * OUTC) return;
    int n = idx / KDIM;
    int k = idx % KDIM;
    int t = k / 64, i = k % 64;
    int x = t / 4, y = t % 4;
    float v;
    if (y < 2) v = ker[(((x * 2 + y) * 64 + i) * 64) + n];
    else       v = -ker[((((3 - x) * 2 + (3 - y)) * 64 + i) * 64) + n];
    uint32_t hb = f2tf32(v);
    float hi = __uint_as_float(hb);
    uint32_t lb = f2tf32(v - hi);
    g_Bhi[n * KDIM + k] = hi;
    g_Blo[n * KDIM + k] = __uint_as_float(lb);
}

// ===================== kernel 4: per-receiver aggregation, cp.async smem pipeline =====================
__global__ void __launch_bounds__(64) k_phase1(const float* __restrict__ feat) {
    __shared__ float sFeat[2][PD][64];
    __shared__ float sW[2][PD][8];

    int warp = threadIdx.x >> 5, lane = threadIdx.x & 31;
    int r = blockIdx.x * 2 + warp;          // grid = NPAD/2 exactly
    int nd = min(g_deg[r], CAP);            // uniform across warp
    size_t base = (size_t)r * CAP;

    int sl = (lane < nd)      ? g_slotS[base + lane]      : 0;
    int sh = (32 + lane < nd) ? g_slotS[base + 32 + lane] : 0;

    float acc[16];
    #pragma unroll
    for (int j = 0; j < 16; j++) acc[j] = 0.f;

    #define ISSUE(e) do {                                                        \
        int _e = (e);                                                            \
        if (_e < nd) {                                                           \
            int _j = _e & (PD - 1);                                              \
            int _s = __shfl_sync(0xFFFFFFFFu, (_e < 32) ? sl : sh, _e & 31);     \
            if (lane < 16) {                                                     \
                const float4* _src = (const float4*)(feat + (size_t)_s * 64) + lane; \
                uint32_t _dst = smem_u32(&sFeat[warp][_j][lane * 4]);            \
                asm volatile("cp.async.ca.shared.global [%0], [%1], 16;"         \
                             :: "r"(_dst), "l"(_src) : "memory");                \
            } else if (lane < 18) {                                              \
                const float4* _src = &g_wp[(base + _e) * 2 + (lane - 16)];       \
                uint32_t _dst = smem_u32(&sW[warp][_j][(lane - 16) * 4]);        \
                asm volatile("cp.async.ca.shared.global [%0], [%1], 16;"         \
                             :: "r"(_dst), "l"(_src) : "memory");                \
            }                                                                    \
        }                                                                        \
        asm volatile("cp.async.commit_group;" ::: "memory");                     \
    } while (0)

    #define CONSUME(e) do {                                                      \
        int _jb = (e) & (PD - 1);                                                \
        float2 f  = *(const float2*)&sFeat[warp][_jb][lane * 2];                 \
        float4 w0 = *(const float4*)&sW[warp][_jb][0];                           \
        float4 w1 = *(const float4*)&sW[warp][_jb][4];                           \
        acc[0]  += w0.x * f.x;  acc[1]  += w0.x * f.y;                           \
        acc[2]  += w0.y * f.x;  acc[3]  += w0.y * f.y;                           \
        acc[4]  += w0.z * f.x;  acc[5]  += w0.z * f.y;                           \
        acc[6]  += w0.w * f.x;  acc[7]  += w0.w * f.y;                           \
        acc[8]  += w1.x * f.x;  acc[9]  += w1.x * f.y;                           \
        acc[10] += w1.y * f.x;  acc[11] += w1.y * f.y;                           \
        acc[12] += w1.z * f.x;  acc[13] += w1.z * f.y;                           \
        acc[14] += w1.w * f.x;  acc[15] += w1.w * f.y;                           \
    } while (0)

    #pragma unroll
    for (int j = 0; j < PD; j++) ISSUE(j);

    int e = 0;
    for (; e + 1 < nd; e += 2) {
        asm volatile("cp.async.wait_group %0;" :: "n"(PD - 2) : "memory");
        __syncwarp();
        CONSUME(e);
        CONSUME(e + 1);
        __syncwarp();
        ISSUE(e + PD);
        ISSUE(e + PD + 1);
    }
    if (e < nd) {
        asm volatile("cp.async.wait_group %0;" :: "n"(PD - 1) : "memory");
        __syncwarp();
        CONSUME(e);
    }
    #undef ISSUE
    #undef CONSUME

    float* dst = g_A + (size_t)r * KDIM + 2 * lane;
    #pragma unroll
    for (int t = 0; t < 8; t++) {
        *(float2*)(dst + t * 64) = make_float2(acc[2 * t], acc[2 * t + 1]);
    }
}

// ===================== kernel 5: tf32 mma GEMM, ldmatrix + double buffer =====================
// out[NPAD(128/CTA), 64] = A[., 512] @ B^T (B stored [n][k]) + bias
// 8 warps as 4(M) x 2(N); warp: 32 rows x 32 cols; KC=32, 16 chunks, 2 smem buffers
static constexpr int KC  = 32;
static constexpr int AST = 36;                // smem row stride (floats), conflict-free
static constexpr int F_AHI = 0;               // per-buffer float offsets
static constexpr int F_ALO = 4608;            // 128*36
static constexpr int F_BHI = 9216;
static constexpr int F_BLO = 11520;           // + 64*36
static constexpr int F_BUF = 13824;           // floats per buffer
static constexpr int GEMM_SMEM = 2 * F_BUF * 4;   // 110592 bytes

__global__ void __launch_bounds__(256) k_gemm(const float* __restrict__ bias,
                                              float* __restrict__ out) {
    extern __shared__ float sm[];

    int tid = threadIdx.x;
    int warp = tid >> 5, lane = tid & 31;
    int gid = lane >> 2, tig = lane & 3;
    int warpM = warp >> 1, warpN = warp & 1;
    int m_base = warpM * 32;
    int n_base = warpN * 32;
    int m0 = blockIdx.x * 128;

    // ldmatrix lane offsets (tile t = lane>>3, row-in-tile = lane&7)
    int t3  = lane >> 3, rin = lane & 7;
    int a_row  = ((t3 & 1) << 3) + rin;       // + 8 for tiles 1,3
    int a_colw = (t3 >> 1) << 2;              // + 4 cols for tiles 2,3
    int b_row  = ((t3 >> 1) << 3) + rin;      // + 8 n for tiles 2,3
    int b_colw = (t3 & 1) << 2;               // + 4 cols for tiles 1,3

    // staging indices: A: 128 rows x 8 float4; B: 64 rows x 8 float4
    int a_srow = tid >> 3, a_sc4 = tid & 7;   // + i*32 rows per iter (4 iters)
    int b_srow = tid >> 3, b_sc4 = tid & 7;   // + i*32 rows per iter (2 iters)

    float acc[2][4][4];
    #pragma unroll
    for (int mt = 0; mt < 2; mt++)
        #pragma unroll
        for (int nt = 0; nt < 4; nt++)
            #pragma unroll
            for (int j = 0; j < 4; j++) acc[mt][nt][j] = 0.f;

    const float4* Ag  = (const float4*)g_A;

    // ---- B cp.async stage for chunk kc into buffer fb ----
    #define STAGE_B(kc, fb) do {                                                 \
        float* _bh = sm + (fb) * F_BUF + F_BHI;                                  \
        float* _bl = sm + (fb) * F_BUF + F_BLO;                                  \
        _Pragma("unroll")                                                        \
        for (int _i = 0; _i < 2; _i++) {                                         \
            int _row = b_srow + _i * 32;                                         \
            const float* _sh = g_Bhi + _row * KDIM + (kc) * KC + b_sc4 * 4;      \
            const float* _slo = g_Blo + _row * KDIM + (kc) * KC + b_sc4 * 4;     \
            uint32_t _dh = smem_u32(_bh + _row * AST + b_sc4 * 4);               \
            uint32_t _dl = smem_u32(_bl + _row * AST + b_sc4 * 4);               \
            asm volatile("cp.async.ca.shared.global [%0], [%1], 16;"             \
                         :: "r"(_dh), "l"(_sh) : "memory");                      \
            asm volatile("cp.async.ca.shared.global [%0], [%1], 16;"             \
                         :: "r"(_dl), "l"(_slo) : "memory");                     \
        }                                                                        \
        asm volatile("cp.async.commit_group;" ::: "memory");                     \
    } while (0)

    // ---- A register load for chunk kc ----
    #define LOAD_A_REGS(kc, av) do {                                             \
        _Pragma("unroll")                                                        \
        for (int _i = 0; _i < 4; _i++) {                                         \
            int _row = a_srow + _i * 32;                                         \
            (av)[_i] = Ag[(size_t)(m0 + _row) * 128 + (kc) * 8 + a_sc4];         \
        }                                                                        \
    } while (0)

    // ---- A split + STS into buffer fb ----
    #define STORE_A(av, fb) do {                                                 \
        float* _ah = sm + (fb) * F_BUF + F_AHI;                                  \
        float* _al = sm + (fb) * F_BUF + F_ALO;                                  \
        _Pragma("unroll")                                                        \
        for (int _i = 0; _i < 4; _i++) {                                         \
            int _row = a_srow + _i * 32;                                         \
            float4 _v = (av)[_i];                                                \
            float4 _hi, _lo;                                                     \
            _hi.x = __uint_as_float(f2tf32(_v.x)); _lo.x = __uint_as_float(f2tf32(_v.x - _hi.x)); \
            _hi.y = __uint_as_float(f2tf32(_v.y)); _lo.y = __uint_as_float(f2tf32(_v.y - _hi.y)); \
            _hi.z = __uint_as_float(f2tf32(_v.z)); _lo.z = __uint_as_float(f2tf32(_v.z - _hi.z)); \
            _hi.w = __uint_as_float(f2tf32(_v.w)); _lo.w = __uint_as_float(f2tf32(_v.w - _hi.w)); \
            *(float4*)(_ah + _row * AST + a_sc4 * 4) = _hi;                      \
            *(float4*)(_al + _row * AST + a_sc4 * 4) = _lo;                      \
        }                                                                        \
    } while (0)

    // ---- prologue: stage chunk 0 into buffer 0 ----
    {
        float4 av[4];
        LOAD_A_REGS(0, av);
        STAGE_B(0, 0);
        STORE_A(av, 0);
        asm volatile("cp.async.wait_group 0;" ::: "memory");
    }
    __syncthreads();

    int buf = 0;
    for (int kc = 0; kc < KDIM / KC; kc++) {
        float4 av[4];
        bool pf = (kc + 1 < KDIM / KC);
        if (pf) {
            LOAD_A_REGS(kc + 1, av);          // LDGs in flight during mma below
            STAGE_B(kc + 1, buf ^ 1);
        }

        // ---- mma on buffer `buf`: 4 k-steps ----
        float* bAhi = sm + buf * F_BUF + F_AHI;
        float* bAlo = sm + buf * F_BUF + F_ALO;
        float* bBhi = sm + buf * F_BUF + F_BHI;
        float* bBlo = sm + buf * F_BUF + F_BLO;
        #pragma unroll
        for (int ks = 0; ks < 4; ks++) {
            int k0 = ks * 8;
            uint32_t ah[2][4], al[2][4], bh[2][4], bl[2][4];
            #pragma unroll
            for (int mt = 0; mt < 2; mt++) {
                int roff = (m_base + mt * 16 + a_row) * AST + k0 + a_colw;
                ldsm4(ah[mt], smem_u32(bAhi + roff));
                ldsm4(al[mt], smem_u32(bAlo + roff));
            }
            #pragma unroll
            for (int pr = 0; pr < 2; pr++) {
                int roff = (n_base + pr * 16 + b_row) * AST + k0 + b_colw;
                ldsm4(bh[pr], smem_u32(bBhi + roff));
                ldsm4(bl[pr], smem_u32(bBlo + roff));
            }
            #pragma unroll
            for (int mt = 0; mt < 2; mt++)
                #pragma unroll
                for (int nt = 0; nt < 4; nt++) {
                    int pr = nt >> 1, of = (nt & 1) * 2;
                    mma8(acc[mt][nt], ah[mt], &bh[pr][of]);
                    mma8(acc[mt][nt], al[mt], &bh[pr][of]);
                    mma8(acc[mt][nt], ah[mt], &bl[pr][of]);
                }
        }

        if (pf) {
            STORE_A(av, buf ^ 1);
            asm volatile("cp.async.wait_group 0;" ::: "memory");
        }
        __syncthreads();
        buf ^= 1;
    }
    #undef STAGE_B
    #undef LOAD_A_REGS
    #undef STORE_A

    // ---- epilogue: bias + store ----
    #pragma unroll
    for (int mt = 0; mt < 2; mt++) {
        int r  = m0 + m_base + mt * 16 + gid;
        int r8 = r + 8;
        #pragma unroll
        for (int nt = 0; nt < 4; nt++) {
            int c = n_base + nt * 8 + tig * 2;
            float b0 = __ldg(bias + c), b1 = __ldg(bias + c + 1);
            if (r < NP) {
                float2 v = make_float2(acc[mt][nt][0] + b0, acc[mt][nt][1] + b1);
                *(float2*)(out + (size_t)r * 64 + c) = v;
            }
            if (r8 < NP) {
                float2 v = make_float2(acc[mt][nt][2] + b0, acc[mt][nt][3] + b1);
                *(float2*)(out + (size_t)r8 * 64 + c) = v;
            }
        }
    }
}

// ===================== launch =====================
extern "C" void kernel_launch(void* const* d_in, const int* in_sizes, int n_in,
                              void* d_out, int out_size) {
    const float* feat = (const float*)d_in[0];
    const int*   recv = (const int*)d_in[1];
    const float* rp   = (const float*)d_in[2];
    const float* ws   = (const float*)d_in[3];
    const int*   snd  = (const int*)d_in[4];
    const float* ker  = (const float*)d_in[5];
    const float* bias = (const float*)d_in[6];
    float* out = (float*)d_out;

    cudaFuncSetAttribute(k_gemm, cudaFuncAttributeMaxDynamicSharedMemorySize, GEMM_SMEM);

    k_zero_deg<<<(NPAD + 255) / 256, 256>>>();
    k_fill<<<(EDG + 255) / 256, 256>>>(recv, snd, rp, ws);
    k_buildB<<<(KDIM * OUTC + 255) / 256, 256>>>(ker);
    k_phase1<<<NPAD / 2, 64>>>(feat);
    k_gemm<<<NPAD / 128, 256, GEMM_SMEM>>>(bias, out);
}

// round 9
// speedup vs baseline: 1.2757x; 1.0456x over previous
#include <cuda_runtime.h>
#include <cstdint>
#include <cstddef>

// ===================== problem constants =====================
static constexpr int NP      = 50000;     // particles
static constexpr int NPAD    = 50048;     // padded to 782*64
static constexpr int EDG     = 800000;
static constexpr int CAP     = 64;        // slots per receiver (Poisson(16) tail-safe)
static constexpr int KDIM    = 512;       // folded contraction dim: 8 taps * 64 ch
static constexpr int OUTC    = 64;
static constexpr int PD      = 8;         // phase1 cp.async pipeline depth

// ===================== device scratch (no allocs allowed) =====================
__device__ int    g_deg[NPAD];
__device__ int    g_slotS[(size_t)NPAD * CAP];        // sender per slot
__device__ float4 g_wp[(size_t)NPAD * CAP * 2];       // folded weights, 2 float4 per slot
__device__ float  g_A[(size_t)NPAD * KDIM];           // folded aggregate [NPAD, 512]
__device__ float  g_Bhi[OUTC * KDIM];                 // tf32-hi folded kernel, [n][k]
__device__ float  g_Blo[OUTC * KDIM];                 // tf32-lo residual,      [n][k]

// ===================== helpers =====================
__device__ __forceinline__ uint32_t f2tf32(float x) {
    uint32_t r;
    asm("cvt.rna.tf32.f32 %0, %1;" : "=r"(r) : "f"(x));
    return r;
}

__device__ __forceinline__ uint32_t smem_u32(const void* p) {
    return (uint32_t)__cvta_generic_to_shared(p);
}

__device__ __forceinline__ void mma8(float* c, const uint32_t* a, const uint32_t* b) {
    asm volatile(
        "mma.sync.aligned.m16n8k8.row.col.f32.tf32.tf32.f32 "
        "{%0,%1,%2,%3}, {%4,%5,%6,%7}, {%8,%9}, {%0,%1,%2,%3};"
        : "+f"(c[0]), "+f"(c[1]), "+f"(c[2]), "+f"(c[3])
        : "r"(a[0]), "r"(a[1]), "r"(a[2]), "r"(a[3]), "r"(b[0]), "r"(b[1]));
}

__device__ __forceinline__ void ldsm4(uint32_t* r, uint32_t addr) {
    asm volatile("ldmatrix.sync.aligned.m8n8.x4.shared.b16 {%0,%1,%2,%3}, [%4];"
                 : "=r"(r[0]), "=r"(r[1]), "=r"(r[2]), "=r"(r[3]) : "r"(addr));
}

// ===================== kernel 1: zero degree counters + build folded B =====================
// B layout [n][k], tf32 hi/lo split. k = t*64+i, t = x*4+y with x in {0,1}.
__global__ void k_prep(const float* __restrict__ ker) {
    int i = blockIdx.x * blockDim.x + threadIdx.x;
    if (i < NPAD) g_deg[i] = 0;
    if (i < KDIM * OUTC) {
        int n = i / KDIM;
        int k = i % KDIM;
        int t = k / 64, ic = k % 64;
        int x = t / 4, y = t % 4;
        float v;
        if (y < 2) v = ker[(((x * 2 + y) * 64 + ic) * 64) + n];
        else       v = -ker[((((3 - x) * 2 + (3 - y)) * 64 + ic) * 64) + n];
        uint32_t hb = f2tf32(v);
        float hi = __uint_as_float(hb);
        uint32_t lb = f2tf32(v - hi);
        g_Bhi[n * KDIM + k] = hi;
        g_Blo[n * KDIM + k] = __uint_as_float(lb);
    }
}

// ===================== kernel 2: bucket edges + precompute folded weights =====================
__global__ void k_fill(const int* __restrict__ recv, const int* __restrict__ snd,
                       const float* __restrict__ rp, const float* __restrict__ ws_p) {
    int e = blockIdx.x * blockDim.x + threadIdx.x;
    if (e >= EDG) return;
    int r = recv[e];
    int slot = atomicAdd(&g_deg[r], 1);
    if (slot >= CAP) return;

    float inv_ws = 1.0f / (*ws_p);
    float2 p = ((const float2*)rp)[e];
    float ux = fminf(fmaxf(p.x * inv_ws, -1.f), 1.f);
    float uy = fminf(fmaxf(p.y * inv_ws, -1.f), 1.f);
    float gx = (ux + 1.f) * 1.5f;
    float gy = (uy + 1.f) * 1.5f;
    float x0 = fminf(fmaxf(floorf(gx), 0.f), 2.f);
    float y0 = fminf(fmaxf(floorf(gy), 0.f), 2.f);
    float fx = gx - x0, fy = gy - y0;
    int x0i = (int)x0, y0i = (int)y0;
    float r2 = ux * ux + uy * uy;
    float win = fmaxf(1.f - r2, 0.f);
    win = win * win * win;

    float wx[4], wy[4];
    #pragma unroll
    for (int j = 0; j < 4; j++) {
        wx[j] = (j == x0i) ? (1.f - fx) * win : ((j == x0i + 1) ? fx * win : 0.f);
        wy[j] = (j == y0i) ? (1.f - fy)       : ((j == y0i + 1) ? fy       : 0.f);
    }
    float wf[8];
    #pragma unroll
    for (int f = 0; f < 8; f++) {
        int xf = f >> 2, yf = f & 3;
        wf[f] = wx[xf] * wy[yf] - wx[3 - xf] * wy[3 - yf];
    }
    size_t si = (size_t)r * CAP + slot;
    g_slotS[si] = snd[e];
    g_wp[si * 2 + 0] = make_float4(wf[0], wf[1], wf[2], wf[3]);
    g_wp[si * 2 + 1] = make_float4(wf[4], wf[5], wf[6], wf[7]);
}

// ===================== kernel 3: per-receiver aggregation, cp.async pipeline, unroll-4 =====================
__global__ void __launch_bounds__(64) k_phase1(const float* __restrict__ feat) {
    __shared__ float sFeat[2][PD][64];
    __shared__ float sW[2][PD][8];

    int warp = threadIdx.x >> 5, lane = threadIdx.x & 31;
    int r = blockIdx.x * 2 + warp;          // grid = NPAD/2 exactly
    int nd = min(g_deg[r], CAP);            // uniform across warp
    size_t base = (size_t)r * CAP;

    int sl = (lane < nd)      ? g_slotS[base + lane]      : 0;
    int sh = (32 + lane < nd) ? g_slotS[base + 32 + lane] : 0;

    float acc[16];
    #pragma unroll
    for (int j = 0; j < 16; j++) acc[j] = 0.f;

    #define ISSUE(e) do {                                                        \
        int _e = (e);                                                            \
        if (_e < nd) {                                                           \
            int _j = _e & (PD - 1);                                              \
            int _s = __shfl_sync(0xFFFFFFFFu, (_e < 32) ? sl : sh, _e & 31);     \
            if (lane < 16) {                                                     \
                const float4* _src = (const float4*)(feat + (size_t)_s * 64) + lane; \
                uint32_t _dst = smem_u32(&sFeat[warp][_j][lane * 4]);            \
                asm volatile("cp.async.ca.shared.global [%0], [%1], 16;"         \
                             :: "r"(_dst), "l"(_src) : "memory");                \
            } else if (lane < 18) {                                              \
                const float4* _src = &g_wp[(base + _e) * 2 + (lane - 16)];       \
                uint32_t _dst = smem_u32(&sW[warp][_j][(lane - 16) * 4]);        \
                asm volatile("cp.async.ca.shared.global [%0], [%1], 16;"         \
                             :: "r"(_dst), "l"(_src) : "memory");                \
            }                                                                    \
        }                                                                        \
        asm volatile("cp.async.commit_group;" ::: "memory");                     \
    } while (0)

    #define CONSUME(e) do {                                                      \
        int _jb = (e) & (PD - 1);                                                \
        float2 f  = *(const float2*)&sFeat[warp][_jb][lane * 2];                 \
        float4 w0 = *(const float4*)&sW[warp][_jb][0];                           \
        float4 w1 = *(const float4*)&sW[warp][_jb][4];                           \
        acc[0]  += w0.x * f.x;  acc[1]  += w0.x * f.y;                           \
        acc[2]  += w0.y * f.x;  acc[3]  += w0.y * f.y;                           \
        acc[4]  += w0.z * f.x;  acc[5]  += w0.z * f.y;                           \
        acc[6]  += w0.w * f.x;  acc[7]  += w0.w * f.y;                           \
        acc[8]  += w1.x * f.x;  acc[9]  += w1.x * f.y;                           \
        acc[10] += w1.y * f.x;  acc[11] += w1.y * f.y;                           \
        acc[12] += w1.z * f.x;  acc[13] += w1.z * f.y;                           \
        acc[14] += w1.w * f.x;  acc[15] += w1.w * f.y;                           \
    } while (0)

    #pragma unroll
    for (int j = 0; j < PD; j++) ISSUE(j);

    int e = 0;
    for (; e + 3 < nd; e += 4) {
        asm volatile("cp.async.wait_group %0;" :: "n"(PD - 4) : "memory");
        __syncwarp();
        CONSUME(e);
        CONSUME(e + 1);
        CONSUME(e + 2);
        CONSUME(e + 3);
        __syncwarp();
        ISSUE(e + PD);
        ISSUE(e + PD + 1);
        ISSUE(e + PD + 2);
        ISSUE(e + PD + 3);
    }
    if (e < nd) {
        asm volatile("cp.async.wait_group 0;" ::: "memory");
        __syncwarp();
        for (; e < nd; e++) CONSUME(e);
    }
    #undef ISSUE
    #undef CONSUME

    float* dst = g_A + (size_t)r * KDIM + 2 * lane;
    #pragma unroll
    for (int t = 0; t < 8; t++) {
        *(float2*)(dst + t * 64) = make_float2(acc[2 * t], acc[2 * t + 1]);
    }
}

// ===================== kernel 4: tf32 mma GEMM, M=64 tiles, 2 CTA/SM =====================
// out[NPAD(64/CTA), 64] = A[., 512] @ B^T (B stored [n][k]) + bias
// 8 warps as 2(M) x 4(N); warp: 32 rows x 16 cols; KC=32, 16 chunks, 2 smem buffers
static constexpr int KC  = 32;
static constexpr int AST = 36;                 // smem row stride (floats), conflict-free
static constexpr int F_AHI = 0;                // per-buffer float offsets
static constexpr int F_ALO = 2304;             // 64*36
static constexpr int F_BHI = 4608;
static constexpr int F_BLO = 6912;
static constexpr int F_BUF = 9216;             // floats per buffer (36 KB)
static constexpr int GEMM_SMEM = 2 * F_BUF * 4;    // 73728 bytes -> 2 CTAs/SM

__global__ void __launch_bounds__(256, 2) k_gemm(const float* __restrict__ bias,
                                                 float* __restrict__ out) {
    extern __shared__ float sm[];

    int tid = threadIdx.x;
    int warp = tid >> 5, lane = tid & 31;
    int gid = lane >> 2, tig = lane & 3;
    int warpM = warp >> 2, warpN = warp & 3;
    int m_base = warpM * 32;
    int n_base = warpN * 16;
    int m0 = blockIdx.x * 64;

    // ldmatrix lane->tile mapping (tile t3 = lane>>3, row-in-tile = lane&7)
    int t3  = lane >> 3, rin = lane & 7;
    int a_row  = ((t3 & 1) << 3) + rin;        // tiles 1,3: +8 rows
    int a_colw = (t3 >> 1) << 2;               // tiles 2,3: +4 k
    int b_row  = ((t3 >> 1) << 3) + rin;       // tiles 2,3: +8 n
    int b_colw = (t3 & 1) << 2;                // tiles 1,3: +4 k

    // staging: 64 rows x 8 float4 per matrix; 256 threads -> 2 iters
    int srow = tid >> 3, sc4 = tid & 7;

    float acc[2][2][4];
    #pragma unroll
    for (int mt = 0; mt < 2; mt++)
        #pragma unroll
        for (int nt = 0; nt < 2; nt++)
            #pragma unroll
            for (int j = 0; j < 4; j++) acc[mt][nt][j] = 0.f;

    const float4* Ag = (const float4*)g_A;

    #define STAGE_B(kc, fb) do {                                                 \
        float* _bh = sm + (fb) * F_BUF + F_BHI;                                  \
        float* _bl = sm + (fb) * F_BUF + F_BLO;                                  \
        _Pragma("unroll")                                                        \
        for (int _i = 0; _i < 2; _i++) {                                         \
            int _row = srow + _i * 32;                                           \
            const float* _sh = g_Bhi + _row * KDIM + (kc) * KC + sc4 * 4;        \
            const float* _slo = g_Blo + _row * KDIM + (kc) * KC + sc4 * 4;       \
            uint32_t _dh = smem_u32(_bh + _row * AST + sc4 * 4);                 \
            uint32_t _dl = smem_u32(_bl + _row * AST + sc4 * 4);                 \
            asm volatile("cp.async.ca.shared.global [%0], [%1], 16;"             \
                         :: "r"(_dh), "l"(_sh) : "memory");                      \
            asm volatile("cp.async.ca.shared.global [%0], [%1], 16;"             \
                         :: "r"(_dl), "l"(_slo) : "memory");                     \
        }                                                                        \
        asm volatile("cp.async.commit_group;" ::: "memory");                     \
    } while (0)

    #define LOAD_A_REGS(kc, av) do {                                             \
        _Pragma("unroll")                                                        \
        for (int _i = 0; _i < 2; _i++) {                                         \
            int _row = srow + _i * 32;                                           \
            (av)[_i] = Ag[(size_t)(m0 + _row) * 128 + (kc) * 8 + sc4];           \
        }                                                                        \
    } while (0)

    #define STORE_A(av, fb) do {                                                 \
        float* _ah = sm + (fb) * F_BUF + F_AHI;                                  \
        float* _al = sm + (fb) * F_BUF + F_ALO;                                  \
        _Pragma("unroll")                                                        \
        for (int _i = 0; _i < 2; _i++) {                                         \
            int _row = srow + _i * 32;                                           \
            float4 _v = (av)[_i];                                                \
            float4 _hi, _lo;                                                     \
            _hi.x = __uint_as_float(f2tf32(_v.x)); _lo.x = __uint_as_float(f2tf32(_v.x - _hi.x)); \
            _hi.y = __uint_as_float(f2tf32(_v.y)); _lo.y = __uint_as_float(f2tf32(_v.y - _hi.y)); \
            _hi.z = __uint_as_float(f2tf32(_v.z)); _lo.z = __uint_as_float(f2tf32(_v.z - _hi.z)); \
            _hi.w = __uint_as_float(f2tf32(_v.w)); _lo.w = __uint_as_float(f2tf32(_v.w - _hi.w)); \
            *(float4*)(_ah + _row * AST + sc4 * 4) = _hi;                        \
            *(float4*)(_al + _row * AST + sc4 * 4) = _lo;                        \
        }                                                                        \
    } while (0)

    // ---- prologue: stage chunk 0 into buffer 0 ----
    {
        float4 av[2];
        LOAD_A_REGS(0, av);
        STAGE_B(0, 0);
        STORE_A(av, 0);
        asm volatile("cp.async.wait_group 0;" ::: "memory");
    }
    __syncthreads();

    int buf = 0;
    for (int kc = 0; kc < KDIM / KC; kc++) {
        float4 av[2];
        bool pf = (kc + 1 < KDIM / KC);
        if (pf) {
            LOAD_A_REGS(kc + 1, av);           // LDGs in flight during mma below
            STAGE_B(kc + 1, buf ^ 1);
        }

        // ---- mma on buffer `buf`: 4 k-steps ----
        float* bAhi = sm + buf * F_BUF + F_AHI;
        float* bAlo = sm + buf * F_BUF + F_ALO;
        float* bBhi = sm + buf * F_BUF + F_BHI;
        float* bBlo = sm + buf * F_BUF + F_BLO;
        #pragma unroll
        for (int ks = 0; ks < 4; ks++) {
            int k0 = ks * 8;
            uint32_t ah[2][4], al[2][4], bh[4], bl[4];
            #pragma unroll
            for (int mt = 0; mt < 2; mt++) {
                int roff = (m_base + mt * 16 + a_row) * AST + k0 + a_colw;
                ldsm4(ah[mt], smem_u32(bAhi + roff));
                ldsm4(al[mt], smem_u32(bAlo + roff));
            }
            {
                int roff = (n_base + b_row) * AST + k0 + b_colw;
                ldsm4(bh, smem_u32(bBhi + roff));
                ldsm4(bl, smem_u32(bBlo + roff));
            }
            #pragma unroll
            for (int mt = 0; mt < 2; mt++)
                #pragma unroll
                for (int nt = 0; nt < 2; nt++) {
                    mma8(acc[mt][nt], ah[mt], &bh[nt * 2]);
                    mma8(acc[mt][nt], al[mt], &bh[nt * 2]);
                    mma8(acc[mt][nt], ah[mt], &bl[nt * 2]);
                }
        }

        if (pf) {
            STORE_A(av, buf ^ 1);
            asm volatile("cp.async.wait_group 0;" ::: "memory");
        }
        __syncthreads();
        buf ^= 1;
    }
    #undef STAGE_B
    #undef LOAD_A_REGS
    #undef STORE_A

    // ---- epilogue: bias + store ----
    #pragma unroll
    for (int mt = 0; mt < 2; mt++) {
        int r  = m0 + m_base + mt * 16 + gid;
        int r8 = r + 8;
        #pragma unroll
        for (int nt = 0; nt < 2; nt++) {
            int c = n_base + nt * 8 + tig * 2;
            float b0 = __ldg(bias + c), b1 = __ldg(bias + c + 1);
            if (r < NP) {
                float2 v = make_float2(acc[mt][nt][0] + b0, acc[mt][nt][1] + b1);
                *(float2*)(out + (size_t)r * 64 + c) = v;
            }
            if (r8 < NP) {
                float2 v = make_float2(acc[mt][nt][2] + b0, acc[mt][nt][3] + b1);
                *(float2*)(out + (size_t)r8 * 64 + c) = v;
            }
        }
    }
}

// ===================== launch =====================
extern "C" void kernel_launch(void* const* d_in, const int* in_sizes, int n_in,
                              void* d_out, int out_size) {
    const float* feat = (const float*)d_in[0];
    const int*   recv = (const int*)d_in[1];
    const float* rp   = (const float*)d_in[2];
    const float* ws   = (const float*)d_in[3];
    const int*   snd  = (const int*)d_in[4];
    const float* ker  = (const float*)d_in[5];
    const float* bias = (const float*)d_in[6];
    float* out = (float*)d_out;

    cudaFuncSetAttribute(k_gemm, cudaFuncAttributeMaxDynamicSharedMemorySize, GEMM_SMEM);

    k_prep<<<(NPAD + 255) / 256, 256>>>(ker);
    k_fill<<<(EDG + 255) / 256, 256>>>(recv, snd, rp, ws);
    k_phase1<<<NPAD / 2, 64>>>(feat);
    k_gemm<<<NPAD / 64, 256, GEMM_SMEM>>>(bias, out);
}